// round 11
// baseline (speedup 1.0000x reference)
#include <cuda_runtime.h>
#include <cuda_bf16.h>
#include <math.h>
#include <cstdint>

// Problem constants
#define BB 8
#define SS 2048
#define DD 1024
#define HH 128
#define MTOT (BB*SS)   // 16384

// ---------------------------------------------------------------------------
// Scratch (__device__ globals; no allocation allowed)
// ---------------------------------------------------------------------------
__device__ __nv_bfloat16 g_xhi[(size_t)MTOT*DD];
__device__ __nv_bfloat16 g_xlo[(size_t)MTOT*DD];
__device__ __nv_bfloat16 g_whi[(size_t)3*HH*DD];  // [w][n][k]
__device__ __nv_bfloat16 g_wlo[(size_t)3*HH*DD];

// QKV outputs, bf16 hi/lo split:
__device__ __nv_bfloat16 g_qhi[(size_t)MTOT*HH];  // [b][s][h], pre-scaled x32
__device__ __nv_bfloat16 g_qlo[(size_t)MTOT*HH];
__device__ __nv_bfloat16 g_khi[(size_t)MTOT*HH];  // [b][s][h]
__device__ __nv_bfloat16 g_klo[(size_t)MTOT*HH];
__device__ __nv_bfloat16 g_vthi[(size_t)BB*HH*SS]; // [b][h][s] (transposed)
__device__ __nv_bfloat16 g_vtlo[(size_t)BB*HH*SS];

// ---------------------------------------------------------------------------
// helpers
// ---------------------------------------------------------------------------
__device__ __forceinline__ uint32_t smem_u32(const void* p) {
    uint32_t a;
    asm("{ .reg .u64 t; cvta.to.shared.u64 t, %1; cvt.u32.u64 %0, t; }" : "=r"(a) : "l"(p));
    return a;
}
__device__ __forceinline__ void ldsm_x4(uint32_t* r, uint32_t addr) {
    asm volatile("ldmatrix.sync.aligned.m8n8.x4.shared.b16 {%0,%1,%2,%3}, [%4];"
                 : "=r"(r[0]), "=r"(r[1]), "=r"(r[2]), "=r"(r[3]) : "r"(addr));
}
__device__ __forceinline__ void mma16816(float* c, const uint32_t* a, const uint32_t* b) {
    asm volatile(
        "mma.sync.aligned.m16n8k16.row.col.f32.bf16.bf16.f32 "
        "{%0,%1,%2,%3}, {%4,%5,%6,%7}, {%8,%9}, {%0,%1,%2,%3};"
        : "+f"(c[0]), "+f"(c[1]), "+f"(c[2]), "+f"(c[3])
        : "r"(a[0]), "r"(a[1]), "r"(a[2]), "r"(a[3]), "r"(b[0]), "r"(b[1]));
}
__device__ __forceinline__ uint32_t pack_bf16(float lo_el, float hi_el) {
    uint32_t r;
    asm("cvt.rn.bf16x2.f32 %0, %1, %2;" : "=r"(r) : "f"(hi_el), "f"(lo_el));
    return r;
}
#define CP_ASYNC16(dst, src) \
    asm volatile("cp.async.cg.shared.global [%0], [%1], 16;" :: "r"(dst), "l"(src))
#define CP_COMMIT() asm volatile("cp.async.commit_group;" ::: "memory")
#define CP_WAIT1()  asm volatile("cp.async.wait_group 1;" ::: "memory")
#define CP_WAIT0()  asm volatile("cp.async.wait_group 0;" ::: "memory")

// ---------------------------------------------------------------------------
// Split-conversion kernels
// ---------------------------------------------------------------------------
__global__ void convert_x(const float* __restrict__ x) {
    size_t i = (size_t)blockIdx.x * blockDim.x + threadIdx.x;  // float4 index
    const float4 v = ((const float4*)x)[i];
    float a[4] = {v.x, v.y, v.z, v.w};
#pragma unroll
    for (int j = 0; j < 4; j++) {
        __nv_bfloat16 hi = __float2bfloat16(a[j]);
        __nv_bfloat16 lo = __float2bfloat16(a[j] - __bfloat162float(hi));
        g_xhi[i * 4 + j] = hi;
        g_xlo[i * 4 + j] = lo;
    }
}
__global__ void convert_w(const float* __restrict__ Wq, const float* __restrict__ Wk,
                          const float* __restrict__ Wv) {
    int idx = blockIdx.x * blockDim.x + threadIdx.x;   // [w][n][k]
    if (idx >= 3 * HH * DD) return;
    int wi = idx / (HH * DD);
    int rem = idx % (HH * DD);
    int n = rem / DD, k = rem % DD;
    const float* W = (wi == 0) ? Wq : (wi == 1) ? Wk : Wv;
    float val = W[(size_t)k * HH + n];
    __nv_bfloat16 hi = __float2bfloat16(val);
    __nv_bfloat16 lo = __float2bfloat16(val - __bfloat162float(hi));
    g_whi[idx] = hi;
    g_wlo[idx] = lo;
}

// ---------------------------------------------------------------------------
// QKV projection via warp-level bf16 split MMA.  128x128 tile, 8 warps,
// 2 CTAs/SM.  (unchanged from R7)
// ---------------------------------------------------------------------------
#define BK 32
#define ROWB 80
#define BUFB (128 * ROWB)
#define QKV_SMEM (2 * 4 * BUFB)   // 81920

__global__ __launch_bounds__(256, 2)
void qkv_mma(const float* __restrict__ bq, const float* __restrict__ bk,
             const float* __restrict__ bv)
{
    extern __shared__ char smc[];
    const int tid  = threadIdx.x;
    const int lane = tid & 31;
    const int w    = tid >> 5;
    const int wm   = w & 3;
    const int wn   = w >> 2;
    const int which = blockIdx.y;
    const int m0 = blockIdx.x * 128;

    const __nv_bfloat16* srcA_hi = g_xhi + (size_t)m0 * DD;
    const __nv_bfloat16* srcA_lo = g_xlo + (size_t)m0 * DD;
    const __nv_bfloat16* srcB_hi = g_whi + (size_t)which * HH * DD;
    const __nv_bfloat16* srcB_lo = g_wlo + (size_t)which * HH * DD;
    const float* bias = (which == 0) ? bq : (which == 1) ? bk : bv;

    const uint32_t smem_base = smem_u32(smc);

    float acc[2][8][4];
#pragma unroll
    for (int mi = 0; mi < 2; mi++)
#pragma unroll
        for (int nt = 0; nt < 8; nt++)
#pragma unroll
            for (int e = 0; e < 4; e++) acc[mi][nt][e] = 0.f;

    const int ldrow0 = tid >> 2;
    const int ldrow1 = (tid + 256) >> 2;
    const int ldpart = tid & 3;

    auto load_stage = [&](int stage, int k0) {
        const __nv_bfloat16* srcs[4] = {srcA_hi, srcA_lo, srcB_hi, srcB_lo};
#pragma unroll
        for (int b = 0; b < 4; b++) {
            uint32_t dbase = smem_base + (uint32_t)(stage * 4 + b) * BUFB;
            CP_ASYNC16(dbase + ldrow0 * ROWB + ldpart * 16,
                       srcs[b] + (size_t)ldrow0 * DD + k0 + ldpart * 8);
            CP_ASYNC16(dbase + ldrow1 * ROWB + ldpart * 16,
                       srcs[b] + (size_t)ldrow1 * DD + k0 + ldpart * 8);
        }
    };

    load_stage(0, 0);
    CP_COMMIT();

    const int NIT = DD / BK;
    for (int it = 0; it < NIT; it++) {
        if (it + 1 < NIT) {
            load_stage((it + 1) & 1, (it + 1) * BK);
            CP_COMMIT();
            CP_WAIT1();
        } else {
            CP_WAIT0();
        }
        __syncthreads();

        const uint32_t stb = smem_base + (uint32_t)((it & 1) * 4) * BUFB;
        const uint32_t pAhi = stb;
        const uint32_t pAlo = stb + BUFB;
        const uint32_t pBhi = stb + 2 * BUFB;
        const uint32_t pBlo = stb + 3 * BUFB;

#pragma unroll
        for (int ks = 0; ks < BK; ks += 16) {
            uint32_t ahi[2][4], alo[2][4];
#pragma unroll
            for (int mi = 0; mi < 2; mi++) {
                int row = wm * 32 + mi * 16 + (lane & 15);
                uint32_t off = (uint32_t)row * ROWB + (uint32_t)(ks + 8 * (lane >> 4)) * 2;
                ldsm_x4(ahi[mi], pAhi + off);
                ldsm_x4(alo[mi], pAlo + off);
            }
#pragma unroll
            for (int nt2 = 0; nt2 < 4; nt2++) {
                int j = lane >> 3;
                int nrow = wn * 64 + nt2 * 16 + 8 * (j >> 1) + (lane & 7);
                uint32_t boff = (uint32_t)nrow * ROWB + (uint32_t)(ks + 8 * (j & 1)) * 2;
                uint32_t bh[4], bl[4];
                ldsm_x4(bh, pBhi + boff);
                ldsm_x4(bl, pBlo + boff);
                mma16816(acc[0][nt2 * 2],     ahi[0], bh);
                mma16816(acc[1][nt2 * 2],     ahi[1], bh);
                mma16816(acc[0][nt2 * 2 + 1], ahi[0], bh + 2);
                mma16816(acc[1][nt2 * 2 + 1], ahi[1], bh + 2);
                mma16816(acc[0][nt2 * 2],     alo[0], bh);
                mma16816(acc[1][nt2 * 2],     alo[1], bh);
                mma16816(acc[0][nt2 * 2 + 1], alo[0], bh + 2);
                mma16816(acc[1][nt2 * 2 + 1], alo[1], bh + 2);
                mma16816(acc[0][nt2 * 2],     ahi[0], bl);
                mma16816(acc[1][nt2 * 2],     ahi[1], bl);
                mma16816(acc[0][nt2 * 2 + 1], ahi[0], bl + 2);
                mma16816(acc[1][nt2 * 2 + 1], ahi[1], bl + 2);
            }
        }
        __syncthreads();
    }

    // ---- epilogue: stage hi/lo bf16 tile in smem, write coalesced ----
    const int b  = m0 / SS;
    const int s0 = m0 % SS;
    const int MSTR = 136;
    __nv_bfloat16* sst = (__nv_bfloat16*)smc;
    const uint32_t lo_base = 128 * MSTR;

#pragma unroll
    for (int mi = 0; mi < 2; mi++) {
#pragma unroll
        for (int half = 0; half < 2; half++) {
            int m = wm * 32 + mi * 16 + (lane >> 2) + 8 * half;
#pragma unroll
            for (int nt = 0; nt < 8; nt++) {
                int n = wn * 64 + nt * 8 + (lane & 3) * 2;
                float v0 = acc[mi][nt][half * 2 + 0] + bias[n];
                float v1 = acc[mi][nt][half * 2 + 1] + bias[n + 1];
                if (which == 0) { v0 *= 32.f; v1 *= 32.f; }
                __nv_bfloat16 h0 = __float2bfloat16(v0);
                __nv_bfloat16 h1 = __float2bfloat16(v1);
                __nv_bfloat16 l0 = __float2bfloat16(v0 - __bfloat162float(h0));
                __nv_bfloat16 l1 = __float2bfloat16(v1 - __bfloat162float(h1));
                if (which < 2) {
                    __nv_bfloat162 ph; ph.x = h0; ph.y = h1;
                    __nv_bfloat162 pl; pl.x = l0; pl.y = l1;
                    *(__nv_bfloat162*)&sst[m * MSTR + n] = ph;
                    *(__nv_bfloat162*)&sst[lo_base + m * MSTR + n] = pl;
                } else {
                    sst[n * MSTR + m] = h0;
                    sst[(n + 1) * MSTR + m] = h1;
                    sst[lo_base + n * MSTR + m] = l0;
                    sst[lo_base + (n + 1) * MSTR + m] = l1;
                }
            }
        }
    }
    __syncthreads();

    __nv_bfloat16* dhi = (which == 0) ? g_qhi : (which == 1) ? g_khi : g_vthi;
    __nv_bfloat16* dlo = (which == 0) ? g_qlo : (which == 1) ? g_klo : g_vtlo;
    const size_t rstride = (which < 2) ? (size_t)HH : (size_t)SS;
    const size_t gbase = (which < 2) ? (((size_t)b * SS + s0) * HH)
                                     : ((size_t)b * HH * SS + s0);
#pragma unroll
    for (int it = 0; it < 16; it++) {
        int idx = it * 256 + tid;
        int arr = idx >> 11;
        int rem = idx & 2047;
        int row = rem >> 4;
        int c   = rem & 15;
        uint4 val = *(const uint4*)&sst[(uint32_t)arr * lo_base + row * MSTR + c * 8];
        __nv_bfloat16* dst = (arr ? dlo : dhi) + gbase + (size_t)row * rstride + c * 8;
        *(uint4*)dst = val;
    }
}

// ---------------------------------------------------------------------------
// Flash attention: TQ=128 (8 warps, 16 rows/warp), TK=64.
// RACE-FREE pipeline: prefetch of KV(kt+1) is issued AFTER the top-of-iter
// __syncthreads (all warps provably done reading stage (kt+1)&1), and waited
// with CP_WAIT0 at the next iteration's top. One commit/wait/sync per tile.
// ---------------------------------------------------------------------------
#define ATQ 128
#define ATK 64
#define KROWB 272   // Q/K smem row stride (256B + 16B pad)
#define VROWB 144   // V smem row stride (128B + 16B pad)
#define QB (128*KROWB)           // one Q array: 34816
#define K_OFF (2*QB)             // 69632
#define KB (64*KROWB)            // one K array: 17408
#define KSTG (2*KB)              // K stage (hi+lo): 34816
#define V_OFF (K_OFF + 2*KSTG)   // 139264
#define VB (128*VROWB)           // one V array: 18432
#define VSTG (2*VB)              // 36864
#define ATTN_SMEM (V_OFF + 2*VSTG)   // 212992

__global__ __launch_bounds__(256, 1)
void attn_mma(float* __restrict__ out)
{
    extern __shared__ char smc[];
    const uint32_t sb = smem_u32(smc);
    const int tid  = threadIdx.x;
    const int lane = tid & 31;
    const int w    = tid >> 5;                 // 0..7, rows w*16..w*16+15
    const int b    = blockIdx.y;
    const int qt   = (int)gridDim.x - 1 - (int)blockIdx.x;  // heavy first
    const int q0   = qt * ATQ;
    const int NK   = 2 * qt + 2;

    // ---- issue Q tile loads (hi+lo): 128 rows x 16 chunks x 2 arrays ----
    {
        const __nv_bfloat16* qhib = g_qhi + ((size_t)b * SS + q0) * HH;
        const __nv_bfloat16* qlob = g_qlo + ((size_t)b * SS + q0) * HH;
#pragma unroll
        for (int it = 0; it < 16; it++) {
            int idx = it * 256 + tid;          // 0..4095
            int arr = idx >> 11;
            int rem = idx & 2047;
            int r = rem >> 4, c = rem & 15;
            const __nv_bfloat16* src = (arr ? qlob : qhib) + (size_t)r * HH + c * 8;
            CP_ASYNC16(sb + arr * QB + r * KROWB + c * 16, src);
        }
    }

    auto load_kv = [&](int stg, int ktile) {
        const int k0 = ktile * ATK;
        uint32_t kb = sb + K_OFF + stg * KSTG;
        const __nv_bfloat16* khb = g_khi + ((size_t)b * SS + k0) * HH;
        const __nv_bfloat16* klb = g_klo + ((size_t)b * SS + k0) * HH;
#pragma unroll
        for (int it = 0; it < 8; it++) {
            int idx = it * 256 + tid;          // 0..2047
            int arr = idx >> 10;
            int rem = idx & 1023;
            int r = rem >> 4, c = rem & 15;    // 64 rows x 16 chunks
            const __nv_bfloat16* src = (arr ? klb : khb) + (size_t)r * HH + c * 8;
            CP_ASYNC16(kb + arr * KB + r * KROWB + c * 16, src);
        }
        uint32_t vb = sb + V_OFF + stg * VSTG;
        const __nv_bfloat16* vhb = g_vthi + (size_t)b * HH * SS + k0;
        const __nv_bfloat16* vlb = g_vtlo + (size_t)b * HH * SS + k0;
#pragma unroll
        for (int it = 0; it < 8; it++) {
            int idx = it * 256 + tid;          // 0..2047
            int arr = idx >> 10;
            int rem = idx & 1023;
            int r = rem >> 3, c = rem & 7;     // 128 rows x 8 chunks
            const __nv_bfloat16* src = (arr ? vlb : vhb) + (size_t)r * SS + c * 8;
            CP_ASYNC16(vb + arr * VB + r * VROWB + c * 16, src);
        }
    };

    load_kv(0, 0);
    CP_COMMIT();   // group: Q + KV(stage0)

    float o[16][4];
#pragma unroll
    for (int nt = 0; nt < 16; nt++)
#pragma unroll
        for (int e = 0; e < 4; e++) o[nt][e] = 0.f;
    float m0r = -1e30f, m1r = -1e30f, l0 = 0.f, l1 = 0.f;
    uint32_t qh[8][4], ql[8][4];

    for (int kt = 0; kt < NK; kt++) {
        CP_WAIT0();          // KV(kt) (and Q at kt=0) complete; only group pending
        __syncthreads();     // ALL warps past iteration kt-1's reads

        if (kt == 0) {
            int arow = w * 16 + (lane & 15);
            uint32_t abase = (uint32_t)arow * KROWB + (uint32_t)(8 * (lane >> 4)) * 2;
#pragma unroll
            for (int ks = 0; ks < 8; ks++) {
                ldsm_x4(qh[ks], sb + abase + ks * 32);
                ldsm_x4(ql[ks], sb + QB + abase + ks * 32);
            }
        }

        // ---- prefetch KV(kt+1): safe now (post-barrier), overlaps compute ----
        if (kt + 1 < NK) {
            load_kv((kt + 1) & 1, kt + 1);
            CP_COMMIT();
        }

        const uint32_t kbase = sb + K_OFF + (kt & 1) * KSTG;
        const uint32_t vbase = sb + V_OFF + (kt & 1) * VSTG;

        // warp fully masked for this tile? (all cols > all its rows)
        const bool dead = (kt * ATK > q0 + w * 16 + 15);

        // ---- S = Q K^T (pre-scaled x32) ----
        float S[8][4];
#pragma unroll
        for (int nt = 0; nt < 8; nt++)
#pragma unroll
            for (int e = 0; e < 4; e++) S[nt][e] = dead ? -1e30f : 0.f;

        if (!dead) {
#pragma unroll
            for (int ks = 0; ks < 8; ks++) {
#pragma unroll
                for (int nt2 = 0; nt2 < 4; nt2++) {
                    int j = lane >> 3;
                    int nrow = nt2 * 16 + 8 * (j >> 1) + (lane & 7);
                    uint32_t boff = (uint32_t)nrow * KROWB + (uint32_t)(ks * 16 + 8 * (j & 1)) * 2;
                    uint32_t bh[4], bl[4];
                    ldsm_x4(bh, kbase + boff);
                    ldsm_x4(bl, kbase + KB + boff);
                    mma16816(S[nt2 * 2],     qh[ks], bh);
                    mma16816(S[nt2 * 2 + 1], qh[ks], bh + 2);
                    mma16816(S[nt2 * 2],     ql[ks], bh);
                    mma16816(S[nt2 * 2 + 1], ql[ks], bh + 2);
                    mma16816(S[nt2 * 2],     qh[ks], bl);
                    mma16816(S[nt2 * 2 + 1], qh[ks], bl + 2);
                }
            }
        }

        // ---- causal mask (only tiles that can touch the diagonal) ----
        const int r  = lane >> 2;
        const int c2 = (lane & 3) * 2;
        if (kt >= 2 * qt && !dead) {
            int gr0l = q0 + w * 16 + r;
            int gr1l = gr0l + 8;
            int gc0 = kt * ATK + c2;
#pragma unroll
            for (int nt = 0; nt < 8; nt++) {
                int col0 = gc0 + nt * 8;
                if (col0 > gr0l)     S[nt][0] = -1e30f;
                if (col0 + 1 > gr0l) S[nt][1] = -1e30f;
                if (col0 > gr1l)     S[nt][2] = -1e30f;
                if (col0 + 1 > gr1l) S[nt][3] = -1e30f;
            }
        }

        // ---- online softmax ----
        float mo0 = m0r, mo1 = m1r;
#pragma unroll
        for (int nt = 0; nt < 8; nt++) {
            m0r = fmaxf(m0r, fmaxf(S[nt][0], S[nt][1]));
            m1r = fmaxf(m1r, fmaxf(S[nt][2], S[nt][3]));
        }
        m0r = fmaxf(m0r, __shfl_xor_sync(0xffffffffu, m0r, 1));
        m0r = fmaxf(m0r, __shfl_xor_sync(0xffffffffu, m0r, 2));
        m1r = fmaxf(m1r, __shfl_xor_sync(0xffffffffu, m1r, 1));
        m1r = fmaxf(m1r, __shfl_xor_sync(0xffffffffu, m1r, 2));
        float a0 = __expf(mo0 - m0r);
        float a1 = __expf(mo1 - m1r);
#pragma unroll
        for (int nt = 0; nt < 16; nt++) {
            o[nt][0] *= a0; o[nt][1] *= a0;
            o[nt][2] *= a1; o[nt][3] *= a1;
        }
        float sum0 = 0.f, sum1 = 0.f;
#pragma unroll
        for (int nt = 0; nt < 8; nt++) {
            S[nt][0] = __expf(S[nt][0] - m0r);
            S[nt][1] = __expf(S[nt][1] - m0r);
            S[nt][2] = __expf(S[nt][2] - m1r);
            S[nt][3] = __expf(S[nt][3] - m1r);
            sum0 += S[nt][0] + S[nt][1];
            sum1 += S[nt][2] + S[nt][3];
        }
        l0 = l0 * a0 + sum0;
        l1 = l1 * a1 + sum1;

        if (!dead) {
            // ---- pack P into A-fragments (hi/lo bf16) ----
            uint32_t ph[4][4], pl[4][4];
#pragma unroll
            for (int kp = 0; kp < 4; kp++) {
#pragma unroll
                for (int half = 0; half < 2; half++) {
                    int nt = 2 * kp + half;
                    float p0 = S[nt][0], p1 = S[nt][1];
                    float p2 = S[nt][2], p3 = S[nt][3];
                    float h0 = __bfloat162float(__float2bfloat16(p0));
                    float h1 = __bfloat162float(__float2bfloat16(p1));
                    float h2 = __bfloat162float(__float2bfloat16(p2));
                    float h3 = __bfloat162float(__float2bfloat16(p3));
                    ph[kp][half * 2 + 0] = pack_bf16(h0, h1);
                    ph[kp][half * 2 + 1] = pack_bf16(h2, h3);
                    pl[kp][half * 2 + 0] = pack_bf16(p0 - h0, p1 - h1);
                    pl[kp][half * 2 + 1] = pack_bf16(p2 - h2, p3 - h3);
                }
            }

            // ---- O += P V ----
#pragma unroll
            for (int ks = 0; ks < 4; ks++) {
#pragma unroll
                for (int nt2 = 0; nt2 < 8; nt2++) {
                    int j = lane >> 3;
                    int nrow = nt2 * 16 + 8 * (j >> 1) + (lane & 7);
                    uint32_t boff = (uint32_t)nrow * VROWB + (uint32_t)(ks * 16 + 8 * (j & 1)) * 2;
                    uint32_t vh[4], vl[4];
                    ldsm_x4(vh, vbase + boff);
                    ldsm_x4(vl, vbase + VB + boff);
                    mma16816(o[nt2 * 2],     ph[ks], vh);
                    mma16816(o[nt2 * 2 + 1], ph[ks], vh + 2);
                    mma16816(o[nt2 * 2],     pl[ks], vh);
                    mma16816(o[nt2 * 2 + 1], pl[ks], vh + 2);
                    mma16816(o[nt2 * 2],     ph[ks], vl);
                    mma16816(o[nt2 * 2 + 1], ph[ks], vl + 2);
                }
            }
        }
    }

    // ---- epilogue ----
    l0 += __shfl_xor_sync(0xffffffffu, l0, 1);
    l0 += __shfl_xor_sync(0xffffffffu, l0, 2);
    l1 += __shfl_xor_sync(0xffffffffu, l1, 1);
    l1 += __shfl_xor_sync(0xffffffffu, l1, 2);
    float inv0 = 1.f / l0, inv1 = 1.f / l1;

    const int gr0 = q0 + w * 16 + (lane >> 2);
    const int gr1 = gr0 + 8;
    const int cb  = (lane & 3) * 2;
#pragma unroll
    for (int nt = 0; nt < 16; nt++) {
        int col = nt * 8 + cb;
        float2 v0 = make_float2(o[nt][0] * inv0, o[nt][1] * inv0);
        float2 v1 = make_float2(o[nt][2] * inv1, o[nt][3] * inv1);
        *(float2*)&out[((size_t)b * SS + gr0) * HH + col] = v0;
        *(float2*)&out[((size_t)b * SS + gr1) * HH + col] = v1;
    }
}

// ---------------------------------------------------------------------------
extern "C" void kernel_launch(void* const* d_in, const int* in_sizes, int n_in,
                              void* d_out, int out_size)
{
    const float* x  = (const float*)d_in[0];
    const float* Wq = (const float*)d_in[1];
    const float* bq = (const float*)d_in[2];
    const float* Wk = (const float*)d_in[3];
    const float* bk = (const float*)d_in[4];
    const float* Wv = (const float*)d_in[5];
    const float* bv = (const float*)d_in[6];
    float* out = (float*)d_out;

    cudaFuncSetAttribute(qkv_mma, cudaFuncAttributeMaxDynamicSharedMemorySize, QKV_SMEM);
    cudaFuncSetAttribute(attn_mma, cudaFuncAttributeMaxDynamicSharedMemorySize, ATTN_SMEM);

    convert_x<<<(MTOT * DD / 4) / 256, 256>>>(x);
    convert_w<<<(3 * HH * DD + 255) / 256, 256>>>(Wq, Wk, Wv);
    qkv_mma<<<dim3(MTOT / 128, 3), 256, QKV_SMEM>>>(bq, bk, bv);
    attn_mma<<<dim3(SS / ATQ, BB), 256, ATTN_SMEM>>>(out);
}

// round 13
// speedup vs baseline: 1.1414x; 1.1414x over previous
#include <cuda_runtime.h>
#include <cuda_bf16.h>
#include <math.h>
#include <cstdint>

// Problem constants
#define BB 8
#define SS 2048
#define DD 1024
#define HH 128
#define MTOT (BB*SS)   // 16384

// ---------------------------------------------------------------------------
// Scratch (__device__ globals; no allocation allowed)
// ---------------------------------------------------------------------------
__device__ __nv_bfloat16 g_xhi[(size_t)MTOT*DD];
__device__ __nv_bfloat16 g_xlo[(size_t)MTOT*DD];
__device__ __nv_bfloat16 g_whi[(size_t)3*HH*DD];  // [w][n][k]
__device__ __nv_bfloat16 g_wlo[(size_t)3*HH*DD];

// QKV outputs, bf16 hi/lo split:
__device__ __nv_bfloat16 g_qhi[(size_t)MTOT*HH];  // [b][s][h], pre-scaled x32
__device__ __nv_bfloat16 g_qlo[(size_t)MTOT*HH];
__device__ __nv_bfloat16 g_khi[(size_t)MTOT*HH];  // [b][s][h]
__device__ __nv_bfloat16 g_klo[(size_t)MTOT*HH];
__device__ __nv_bfloat16 g_vthi[(size_t)BB*HH*SS]; // [b][h][s] (transposed)
__device__ __nv_bfloat16 g_vtlo[(size_t)BB*HH*SS];

// split-K attention partials: 40 chunks per batch, 128 rows, 128 cols
#define NCHUNKS_PB 40
__device__ float g_opart[(size_t)BB*NCHUNKS_PB*128*128];   // 21 MB
__device__ float g_mpart[(size_t)BB*NCHUNKS_PB*128];
__device__ float g_lpart[(size_t)BB*NCHUNKS_PB*128];

// ---------------------------------------------------------------------------
// helpers
// ---------------------------------------------------------------------------
__device__ __forceinline__ uint32_t smem_u32(const void* p) {
    uint32_t a;
    asm("{ .reg .u64 t; cvta.to.shared.u64 t, %1; cvt.u32.u64 %0, t; }" : "=r"(a) : "l"(p));
    return a;
}
__device__ __forceinline__ void ldsm_x4(uint32_t* r, uint32_t addr) {
    asm volatile("ldmatrix.sync.aligned.m8n8.x4.shared.b16 {%0,%1,%2,%3}, [%4];"
                 : "=r"(r[0]), "=r"(r[1]), "=r"(r[2]), "=r"(r[3]) : "r"(addr));
}
__device__ __forceinline__ void mma16816(float* c, const uint32_t* a, const uint32_t* b) {
    asm volatile(
        "mma.sync.aligned.m16n8k16.row.col.f32.bf16.bf16.f32 "
        "{%0,%1,%2,%3}, {%4,%5,%6,%7}, {%8,%9}, {%0,%1,%2,%3};"
        : "+f"(c[0]), "+f"(c[1]), "+f"(c[2]), "+f"(c[3])
        : "r"(a[0]), "r"(a[1]), "r"(a[2]), "r"(a[3]), "r"(b[0]), "r"(b[1]));
}
__device__ __forceinline__ uint32_t pack_bf16(float lo_el, float hi_el) {
    uint32_t r;
    asm("cvt.rn.bf16x2.f32 %0, %1, %2;" : "=r"(r) : "f"(hi_el), "f"(lo_el));
    return r;
}
#define CP_ASYNC16(dst, src) \
    asm volatile("cp.async.cg.shared.global [%0], [%1], 16;" :: "r"(dst), "l"(src))
#define CP_COMMIT() asm volatile("cp.async.commit_group;" ::: "memory")
#define CP_WAIT1()  asm volatile("cp.async.wait_group 1;" ::: "memory")
#define CP_WAIT0()  asm volatile("cp.async.wait_group 0;" ::: "memory")

// ---------------------------------------------------------------------------
// Split-conversion kernels
// ---------------------------------------------------------------------------
__global__ void convert_x(const float* __restrict__ x) {
    size_t i = (size_t)blockIdx.x * blockDim.x + threadIdx.x;  // float4 index
    const float4 v = ((const float4*)x)[i];
    float a[4] = {v.x, v.y, v.z, v.w};
#pragma unroll
    for (int j = 0; j < 4; j++) {
        __nv_bfloat16 hi = __float2bfloat16(a[j]);
        __nv_bfloat16 lo = __float2bfloat16(a[j] - __bfloat162float(hi));
        g_xhi[i * 4 + j] = hi;
        g_xlo[i * 4 + j] = lo;
    }
}
__global__ void convert_w(const float* __restrict__ Wq, const float* __restrict__ Wk,
                          const float* __restrict__ Wv) {
    int idx = blockIdx.x * blockDim.x + threadIdx.x;   // [w][n][k]
    if (idx >= 3 * HH * DD) return;
    int wi = idx / (HH * DD);
    int rem = idx % (HH * DD);
    int n = rem / DD, k = rem % DD;
    const float* W = (wi == 0) ? Wq : (wi == 1) ? Wk : Wv;
    float val = W[(size_t)k * HH + n];
    __nv_bfloat16 hi = __float2bfloat16(val);
    __nv_bfloat16 lo = __float2bfloat16(val - __bfloat162float(hi));
    g_whi[idx] = hi;
    g_wlo[idx] = lo;
}

// ---------------------------------------------------------------------------
// QKV projection via warp-level bf16 split MMA.  128x128 tile, 8 warps,
// 2 CTAs/SM.  (unchanged)
// ---------------------------------------------------------------------------
#define BK 32
#define ROWB 80
#define BUFB (128 * ROWB)
#define QKV_SMEM (2 * 4 * BUFB)   // 81920

__global__ __launch_bounds__(256, 2)
void qkv_mma(const float* __restrict__ bq, const float* __restrict__ bk,
             const float* __restrict__ bv)
{
    extern __shared__ char smc[];
    const int tid  = threadIdx.x;
    const int lane = tid & 31;
    const int w    = tid >> 5;
    const int wm   = w & 3;
    const int wn   = w >> 2;
    const int which = blockIdx.y;
    const int m0 = blockIdx.x * 128;

    const __nv_bfloat16* srcA_hi = g_xhi + (size_t)m0 * DD;
    const __nv_bfloat16* srcA_lo = g_xlo + (size_t)m0 * DD;
    const __nv_bfloat16* srcB_hi = g_whi + (size_t)which * HH * DD;
    const __nv_bfloat16* srcB_lo = g_wlo + (size_t)which * HH * DD;
    const float* bias = (which == 0) ? bq : (which == 1) ? bk : bv;

    const uint32_t smem_base = smem_u32(smc);

    float acc[2][8][4];
#pragma unroll
    for (int mi = 0; mi < 2; mi++)
#pragma unroll
        for (int nt = 0; nt < 8; nt++)
#pragma unroll
            for (int e = 0; e < 4; e++) acc[mi][nt][e] = 0.f;

    const int ldrow0 = tid >> 2;
    const int ldrow1 = (tid + 256) >> 2;
    const int ldpart = tid & 3;

    auto load_stage = [&](int stage, int k0) {
        const __nv_bfloat16* srcs[4] = {srcA_hi, srcA_lo, srcB_hi, srcB_lo};
#pragma unroll
        for (int b = 0; b < 4; b++) {
            uint32_t dbase = smem_base + (uint32_t)(stage * 4 + b) * BUFB;
            CP_ASYNC16(dbase + ldrow0 * ROWB + ldpart * 16,
                       srcs[b] + (size_t)ldrow0 * DD + k0 + ldpart * 8);
            CP_ASYNC16(dbase + ldrow1 * ROWB + ldpart * 16,
                       srcs[b] + (size_t)ldrow1 * DD + k0 + ldpart * 8);
        }
    };

    load_stage(0, 0);
    CP_COMMIT();

    const int NIT = DD / BK;
    for (int it = 0; it < NIT; it++) {
        if (it + 1 < NIT) {
            load_stage((it + 1) & 1, (it + 1) * BK);
            CP_COMMIT();
            CP_WAIT1();
        } else {
            CP_WAIT0();
        }
        __syncthreads();

        const uint32_t stb = smem_base + (uint32_t)((it & 1) * 4) * BUFB;
        const uint32_t pAhi = stb;
        const uint32_t pAlo = stb + BUFB;
        const uint32_t pBhi = stb + 2 * BUFB;
        const uint32_t pBlo = stb + 3 * BUFB;

#pragma unroll
        for (int ks = 0; ks < BK; ks += 16) {
            uint32_t ahi[2][4], alo[2][4];
#pragma unroll
            for (int mi = 0; mi < 2; mi++) {
                int row = wm * 32 + mi * 16 + (lane & 15);
                uint32_t off = (uint32_t)row * ROWB + (uint32_t)(ks + 8 * (lane >> 4)) * 2;
                ldsm_x4(ahi[mi], pAhi + off);
                ldsm_x4(alo[mi], pAlo + off);
            }
#pragma unroll
            for (int nt2 = 0; nt2 < 4; nt2++) {
                int j = lane >> 3;
                int nrow = wn * 64 + nt2 * 16 + 8 * (j >> 1) + (lane & 7);
                uint32_t boff = (uint32_t)nrow * ROWB + (uint32_t)(ks + 8 * (j & 1)) * 2;
                uint32_t bh[4], bl[4];
                ldsm_x4(bh, pBhi + boff);
                ldsm_x4(bl, pBlo + boff);
                mma16816(acc[0][nt2 * 2],     ahi[0], bh);
                mma16816(acc[1][nt2 * 2],     ahi[1], bh);
                mma16816(acc[0][nt2 * 2 + 1], ahi[0], bh + 2);
                mma16816(acc[1][nt2 * 2 + 1], ahi[1], bh + 2);
                mma16816(acc[0][nt2 * 2],     alo[0], bh);
                mma16816(acc[1][nt2 * 2],     alo[1], bh);
                mma16816(acc[0][nt2 * 2 + 1], alo[0], bh + 2);
                mma16816(acc[1][nt2 * 2 + 1], alo[1], bh + 2);
                mma16816(acc[0][nt2 * 2],     ahi[0], bl);
                mma16816(acc[1][nt2 * 2],     ahi[1], bl);
                mma16816(acc[0][nt2 * 2 + 1], ahi[0], bl + 2);
                mma16816(acc[1][nt2 * 2 + 1], ahi[1], bl + 2);
            }
        }
        __syncthreads();
    }

    // ---- epilogue: stage hi/lo bf16 tile in smem, write coalesced ----
    const int b  = m0 / SS;
    const int s0 = m0 % SS;
    const int MSTR = 136;
    __nv_bfloat16* sst = (__nv_bfloat16*)smc;
    const uint32_t lo_base = 128 * MSTR;

#pragma unroll
    for (int mi = 0; mi < 2; mi++) {
#pragma unroll
        for (int half = 0; half < 2; half++) {
            int m = wm * 32 + mi * 16 + (lane >> 2) + 8 * half;
#pragma unroll
            for (int nt = 0; nt < 8; nt++) {
                int n = wn * 64 + nt * 8 + (lane & 3) * 2;
                float v0 = acc[mi][nt][half * 2 + 0] + bias[n];
                float v1 = acc[mi][nt][half * 2 + 1] + bias[n + 1];
                if (which == 0) { v0 *= 32.f; v1 *= 32.f; }
                __nv_bfloat16 h0 = __float2bfloat16(v0);
                __nv_bfloat16 h1 = __float2bfloat16(v1);
                __nv_bfloat16 l0 = __float2bfloat16(v0 - __bfloat162float(h0));
                __nv_bfloat16 l1 = __float2bfloat16(v1 - __bfloat162float(h1));
                if (which < 2) {
                    __nv_bfloat162 ph; ph.x = h0; ph.y = h1;
                    __nv_bfloat162 pl; pl.x = l0; pl.y = l1;
                    *(__nv_bfloat162*)&sst[m * MSTR + n] = ph;
                    *(__nv_bfloat162*)&sst[lo_base + m * MSTR + n] = pl;
                } else {
                    sst[n * MSTR + m] = h0;
                    sst[(n + 1) * MSTR + m] = h1;
                    sst[lo_base + n * MSTR + m] = l0;
                    sst[lo_base + (n + 1) * MSTR + m] = l1;
                }
            }
        }
    }
    __syncthreads();

    __nv_bfloat16* dhi = (which == 0) ? g_qhi : (which == 1) ? g_khi : g_vthi;
    __nv_bfloat16* dlo = (which == 0) ? g_qlo : (which == 1) ? g_klo : g_vtlo;
    const size_t rstride = (which < 2) ? (size_t)HH : (size_t)SS;
    const size_t gbase = (which < 2) ? (((size_t)b * SS + s0) * HH)
                                     : ((size_t)b * HH * SS + s0);
#pragma unroll
    for (int it = 0; it < 16; it++) {
        int idx = it * 256 + tid;
        int arr = idx >> 11;
        int rem = idx & 2047;
        int row = rem >> 4;
        int c   = rem & 15;
        uint4 val = *(const uint4*)&sst[(uint32_t)arr * lo_base + row * MSTR + c * 8];
        __nv_bfloat16* dst = (arr ? dlo : dhi) + gbase + (size_t)row * rstride + c * 8;
        *(uint4*)dst = val;
    }
}

// ---------------------------------------------------------------------------
// Split-K flash attention partials: TQ=128 (8 warps), chunks of <=8 k-tiles.
// Race-free pipeline (prefetch post-barrier).  Writes (o, m, l) partials.
// ---------------------------------------------------------------------------
#define ATQ 128
#define ATK 64
#define KROWB 272   // Q/K smem row stride (256B + 16B pad)
#define VROWB 144   // V smem row stride (128B + 16B pad)
#define QB (128*KROWB)           // one Q array: 34816
#define K_OFF (2*QB)             // 69632
#define KB (64*KROWB)            // one K array: 17408
#define KSTG (2*KB)              // K stage (hi+lo): 34816
#define V_OFF (K_OFF + 2*KSTG)   // 139264
#define VB (128*VROWB)           // one V array: 18432
#define VSTG (2*VB)              // 36864
#define ATTN_SMEM (V_OFF + 2*VSTG)   // 212992
#define CHUNK 8                  // k-tiles per chunk

__global__ __launch_bounds__(256, 1)
void attn_mma(void)
{
    extern __shared__ char smc[];
    const uint32_t sb = smem_u32(smc);
    const int tid  = threadIdx.x;
    const int lane = tid & 31;
    const int w    = tid >> 5;                 // 0..7, rows w*16..w*16+15
    const int b    = blockIdx.y;
    const int id   = blockIdx.x;               // chunk id within batch (0..39)

    // ---- map id -> (qt, kstart, kend), qt descending (heavy first) ----
    int qt = 15, kstart = 0, kend = 0;
    {
        int c = id;
        for (int q = 15; q >= 0; q--) {
            int nk = 2 * q + 2;
            int np = (nk + CHUNK - 1) >> 3;
            if (c < np) { qt = q; kstart = c * CHUNK; kend = min(kstart + CHUNK, nk); break; }
            c -= np;
        }
    }
    const int q0 = qt * ATQ;
    const int pid = b * NCHUNKS_PB + id;       // scratch slot

    // ---- issue Q tile loads (hi+lo) ----
    {
        const __nv_bfloat16* qhib = g_qhi + ((size_t)b * SS + q0) * HH;
        const __nv_bfloat16* qlob = g_qlo + ((size_t)b * SS + q0) * HH;
#pragma unroll
        for (int it = 0; it < 16; it++) {
            int idx = it * 256 + tid;          // 0..4095
            int arr = idx >> 11;
            int rem = idx & 2047;
            int r = rem >> 4, c = rem & 15;
            const __nv_bfloat16* src = (arr ? qlob : qhib) + (size_t)r * HH + c * 8;
            CP_ASYNC16(sb + arr * QB + r * KROWB + c * 16, src);
        }
    }

    auto load_kv = [&](int stg, int ktile) {
        const int k0 = ktile * ATK;
        uint32_t kb = sb + K_OFF + stg * KSTG;
        const __nv_bfloat16* khb = g_khi + ((size_t)b * SS + k0) * HH;
        const __nv_bfloat16* klb = g_klo + ((size_t)b * SS + k0) * HH;
#pragma unroll
        for (int it = 0; it < 8; it++) {
            int idx = it * 256 + tid;          // 0..2047
            int arr = idx >> 10;
            int rem = idx & 1023;
            int r = rem >> 4, c = rem & 15;    // 64 rows x 16 chunks
            const __nv_bfloat16* src = (arr ? klb : khb) + (size_t)r * HH + c * 8;
            CP_ASYNC16(kb + arr * KB + r * KROWB + c * 16, src);
        }
        uint32_t vb = sb + V_OFF + stg * VSTG;
        const __nv_bfloat16* vhb = g_vthi + (size_t)b * HH * SS + k0;
        const __nv_bfloat16* vlb = g_vtlo + (size_t)b * HH * SS + k0;
#pragma unroll
        for (int it = 0; it < 8; it++) {
            int idx = it * 256 + tid;          // 0..2047
            int arr = idx >> 10;
            int rem = idx & 1023;
            int r = rem >> 3, c = rem & 7;     // 128 rows x 8 chunks
            const __nv_bfloat16* src = (arr ? vlb : vhb) + (size_t)r * SS + c * 8;
            CP_ASYNC16(vb + arr * VB + r * VROWB + c * 16, src);
        }
    };

    load_kv(kstart & 1, kstart);
    CP_COMMIT();   // group: Q + KV(kstart)

    float o[16][4];
#pragma unroll
    for (int nt = 0; nt < 16; nt++)
#pragma unroll
        for (int e = 0; e < 4; e++) o[nt][e] = 0.f;
    float m0r = -1e30f, m1r = -1e30f, l0 = 0.f, l1 = 0.f;
    uint32_t qh[8][4], ql[8][4];

    for (int kt = kstart; kt < kend; kt++) {
        CP_WAIT0();          // KV(kt) (and Q on first iter) complete
        __syncthreads();     // ALL warps past previous iteration's reads

        if (kt == kstart) {
            int arow = w * 16 + (lane & 15);
            uint32_t abase = (uint32_t)arow * KROWB + (uint32_t)(8 * (lane >> 4)) * 2;
#pragma unroll
            for (int ks = 0; ks < 8; ks++) {
                ldsm_x4(qh[ks], sb + abase + ks * 32);
                ldsm_x4(ql[ks], sb + QB + abase + ks * 32);
            }
        }

        // ---- prefetch KV(kt+1): safe (post-barrier), overlaps compute ----
        if (kt + 1 < kend) {
            load_kv((kt + 1) & 1, kt + 1);
            CP_COMMIT();
        }

        const uint32_t kbase = sb + K_OFF + (kt & 1) * KSTG;
        const uint32_t vbase = sb + V_OFF + (kt & 1) * VSTG;

        // warp fully masked for this tile? (all cols > all its rows)
        const bool dead = (kt * ATK > q0 + w * 16 + 15);

        // ---- S = Q K^T (pre-scaled x32) ----
        float S[8][4];
#pragma unroll
        for (int nt = 0; nt < 8; nt++)
#pragma unroll
            for (int e = 0; e < 4; e++) S[nt][e] = dead ? -1e30f : 0.f;

        if (!dead) {
#pragma unroll
            for (int ks = 0; ks < 8; ks++) {
#pragma unroll
                for (int nt2 = 0; nt2 < 4; nt2++) {
                    int j = lane >> 3;
                    int nrow = nt2 * 16 + 8 * (j >> 1) + (lane & 7);
                    uint32_t boff = (uint32_t)nrow * KROWB + (uint32_t)(ks * 16 + 8 * (j & 1)) * 2;
                    uint32_t bh[4], bl[4];
                    ldsm_x4(bh, kbase + boff);
                    ldsm_x4(bl, kbase + KB + boff);
                    mma16816(S[nt2 * 2],     qh[ks], bh);
                    mma16816(S[nt2 * 2 + 1], qh[ks], bh + 2);
                    mma16816(S[nt2 * 2],     ql[ks], bh);
                    mma16816(S[nt2 * 2 + 1], ql[ks], bh + 2);
                    mma16816(S[nt2 * 2],     qh[ks], bl);
                    mma16816(S[nt2 * 2 + 1], qh[ks], bl + 2);
                }
            }
        }

        // ---- causal mask (only tiles that can touch the diagonal) ----
        const int r  = lane >> 2;
        const int c2 = (lane & 3) * 2;
        if (kt >= 2 * qt && !dead) {
            int gr0l = q0 + w * 16 + r;
            int gr1l = gr0l + 8;
            int gc0 = kt * ATK + c2;
#pragma unroll
            for (int nt = 0; nt < 8; nt++) {
                int col0 = gc0 + nt * 8;
                if (col0 > gr0l)     S[nt][0] = -1e30f;
                if (col0 + 1 > gr0l) S[nt][1] = -1e30f;
                if (col0 > gr1l)     S[nt][2] = -1e30f;
                if (col0 + 1 > gr1l) S[nt][3] = -1e30f;
            }
        }

        // ---- online softmax ----
        float mo0 = m0r, mo1 = m1r;
#pragma unroll
        for (int nt = 0; nt < 8; nt++) {
            m0r = fmaxf(m0r, fmaxf(S[nt][0], S[nt][1]));
            m1r = fmaxf(m1r, fmaxf(S[nt][2], S[nt][3]));
        }
        m0r = fmaxf(m0r, __shfl_xor_sync(0xffffffffu, m0r, 1));
        m0r = fmaxf(m0r, __shfl_xor_sync(0xffffffffu, m0r, 2));
        m1r = fmaxf(m1r, __shfl_xor_sync(0xffffffffu, m1r, 1));
        m1r = fmaxf(m1r, __shfl_xor_sync(0xffffffffu, m1r, 2));
        float a0 = __expf(mo0 - m0r);
        float a1 = __expf(mo1 - m1r);
#pragma unroll
        for (int nt = 0; nt < 16; nt++) {
            o[nt][0] *= a0; o[nt][1] *= a0;
            o[nt][2] *= a1; o[nt][3] *= a1;
        }
        float sum0 = 0.f, sum1 = 0.f;
#pragma unroll
        for (int nt = 0; nt < 8; nt++) {
            S[nt][0] = __expf(S[nt][0] - m0r);
            S[nt][1] = __expf(S[nt][1] - m0r);
            S[nt][2] = __expf(S[nt][2] - m1r);
            S[nt][3] = __expf(S[nt][3] - m1r);
            sum0 += S[nt][0] + S[nt][1];
            sum1 += S[nt][2] + S[nt][3];
        }
        l0 = l0 * a0 + sum0;
        l1 = l1 * a1 + sum1;

        if (!dead) {
            // ---- pack P into A-fragments (hi/lo bf16) ----
            uint32_t ph[4][4], pl[4][4];
#pragma unroll
            for (int kp = 0; kp < 4; kp++) {
#pragma unroll
                for (int half = 0; half < 2; half++) {
                    int nt = 2 * kp + half;
                    float p0 = S[nt][0], p1 = S[nt][1];
                    float p2 = S[nt][2], p3 = S[nt][3];
                    float h0 = __bfloat162float(__float2bfloat16(p0));
                    float h1 = __bfloat162float(__float2bfloat16(p1));
                    float h2 = __bfloat162float(__float2bfloat16(p2));
                    float h3 = __bfloat162float(__float2bfloat16(p3));
                    ph[kp][half * 2 + 0] = pack_bf16(h0, h1);
                    ph[kp][half * 2 + 1] = pack_bf16(h2, h3);
                    pl[kp][half * 2 + 0] = pack_bf16(p0 - h0, p1 - h1);
                    pl[kp][half * 2 + 1] = pack_bf16(p2 - h2, p3 - h3);
                }
            }

            // ---- O += P V ----
#pragma unroll
            for (int ks = 0; ks < 4; ks++) {
#pragma unroll
                for (int nt2 = 0; nt2 < 8; nt2++) {
                    int j = lane >> 3;
                    int nrow = nt2 * 16 + 8 * (j >> 1) + (lane & 7);
                    uint32_t boff = (uint32_t)nrow * VROWB + (uint32_t)(ks * 16 + 8 * (j & 1)) * 2;
                    uint32_t vh[4], vl[4];
                    ldsm_x4(vh, vbase + boff);
                    ldsm_x4(vl, vbase + VB + boff);
                    mma16816(o[nt2 * 2],     ph[ks], vh);
                    mma16816(o[nt2 * 2 + 1], ph[ks], vh + 2);
                    mma16816(o[nt2 * 2],     pl[ks], vh);
                    mma16816(o[nt2 * 2 + 1], pl[ks], vh + 2);
                    mma16816(o[nt2 * 2],     ph[ks], vl);
                    mma16816(o[nt2 * 2 + 1], ph[ks], vl + 2);
                }
            }
        }
    }

    // ---- epilogue: write UNNORMALIZED partial (o, m, l) to scratch ----
    l0 += __shfl_xor_sync(0xffffffffu, l0, 1);
    l0 += __shfl_xor_sync(0xffffffffu, l0, 2);
    l1 += __shfl_xor_sync(0xffffffffu, l1, 1);
    l1 += __shfl_xor_sync(0xffffffffu, l1, 2);

    const int lr0 = w * 16 + (lane >> 2);      // local row in tile
    const int lr1 = lr0 + 8;
    const int cb  = (lane & 3) * 2;
    float* obase = g_opart + (size_t)pid * 128 * 128;
#pragma unroll
    for (int nt = 0; nt < 16; nt++) {
        int col = nt * 8 + cb;
        *(float2*)&obase[(size_t)lr0 * 128 + col] = make_float2(o[nt][0], o[nt][1]);
        *(float2*)&obase[(size_t)lr1 * 128 + col] = make_float2(o[nt][2], o[nt][3]);
    }
    if ((lane & 3) == 0) {
        g_mpart[(size_t)pid * 128 + lr0] = m0r;
        g_mpart[(size_t)pid * 128 + lr1] = m1r;
        g_lpart[(size_t)pid * 128 + lr0] = l0;
        g_lpart[(size_t)pid * 128 + lr1] = l1;
    }
}

// ---------------------------------------------------------------------------
// Combine split-K partials: out = sum_i e^{m_i - M} o_i / sum_i e^{m_i - M} l_i
// grid (16 qtiles, 8 batches), 256 threads: thread = (row, half-of-cols)
// ---------------------------------------------------------------------------
__global__ __launch_bounds__(256)
void attn_combine(float* __restrict__ out)
{
    const int qt = blockIdx.x;
    const int b  = blockIdx.y;
    const int np = (2 * qt + 2 + CHUNK - 1) >> 3;
    int off = 0;
    for (int q = 15; q > qt; q--) off += (2 * q + 2 + CHUNK - 1) >> 3;
    const int pid0 = b * NCHUNKS_PB + off;

    const int tid = threadIdx.x;
    const int row = tid >> 1;                  // 0..127
    const int c0  = (tid & 1) * 64;

    float m[4], lv[4];
    float M = -1e30f;
    for (int p = 0; p < np; p++) {
        m[p]  = g_mpart[(size_t)(pid0 + p) * 128 + row];
        lv[p] = g_lpart[(size_t)(pid0 + p) * 128 + row];
        M = fmaxf(M, m[p]);
    }
    float wgt[4];
    float L = 0.f;
    for (int p = 0; p < np; p++) {
        wgt[p] = __expf(m[p] - M);
        L += wgt[p] * lv[p];
    }
    const float inv = 1.f / L;

    float* dst = out + ((size_t)b * SS + qt * ATQ + row) * HH + c0;
#pragma unroll 4
    for (int c4 = 0; c4 < 16; c4++) {
        float4 acc = make_float4(0.f, 0.f, 0.f, 0.f);
        for (int p = 0; p < np; p++) {
            const float4 v = *(const float4*)&g_opart[((size_t)(pid0 + p) * 128 + row) * 128 + c0 + c4 * 4];
            acc.x += wgt[p] * v.x;
            acc.y += wgt[p] * v.y;
            acc.z += wgt[p] * v.z;
            acc.w += wgt[p] * v.w;
        }
        acc.x *= inv; acc.y *= inv; acc.z *= inv; acc.w *= inv;
        *(float4*)&dst[c4 * 4] = acc;
    }
}

// ---------------------------------------------------------------------------
extern "C" void kernel_launch(void* const* d_in, const int* in_sizes, int n_in,
                              void* d_out, int out_size)
{
    const float* x  = (const float*)d_in[0];
    const float* Wq = (const float*)d_in[1];
    const float* bq = (const float*)d_in[2];
    const float* Wk = (const float*)d_in[3];
    const float* bk = (const float*)d_in[4];
    const float* Wv = (const float*)d_in[5];
    const float* bv = (const float*)d_in[6];
    float* out = (float*)d_out;

    cudaFuncSetAttribute(qkv_mma, cudaFuncAttributeMaxDynamicSharedMemorySize, QKV_SMEM);
    cudaFuncSetAttribute(attn_mma, cudaFuncAttributeMaxDynamicSharedMemorySize, ATTN_SMEM);

    convert_x<<<(MTOT * DD / 4) / 256, 256>>>(x);
    convert_w<<<(3 * HH * DD + 255) / 256, 256>>>(Wq, Wk, Wv);
    qkv_mma<<<dim3(MTOT / 128, 3), 256, QKV_SMEM>>>(bq, bk, bv);
    attn_mma<<<dim3(NCHUNKS_PB, BB), 256, ATTN_SMEM>>>();
    attn_combine<<<dim3(SS / ATQ, BB), 256>>>(out);
}

// round 16
// speedup vs baseline: 1.1543x; 1.0113x over previous
#include <cuda_runtime.h>
#include <cuda_bf16.h>
#include <math.h>
#include <cstdint>

// Problem constants
#define BB 8
#define SS 2048
#define DD 1024
#define HH 128
#define MTOT (BB*SS)   // 16384

// ---------------------------------------------------------------------------
// Scratch (__device__ globals; no allocation allowed)
// ---------------------------------------------------------------------------
__device__ __nv_bfloat16 g_xhi[(size_t)MTOT*DD];
__device__ __nv_bfloat16 g_xlo[(size_t)MTOT*DD];
__device__ __nv_bfloat16 g_whi[(size_t)3*HH*DD];  // [w][n][k]
__device__ __nv_bfloat16 g_wlo[(size_t)3*HH*DD];

// QKV outputs, bf16 hi/lo split:
__device__ __nv_bfloat16 g_qhi[(size_t)MTOT*HH];  // [b][s][h], pre-scaled x32
__device__ __nv_bfloat16 g_qlo[(size_t)MTOT*HH];
__device__ __nv_bfloat16 g_khi[(size_t)MTOT*HH];  // [b][s][h]
__device__ __nv_bfloat16 g_klo[(size_t)MTOT*HH];
__device__ __nv_bfloat16 g_vthi[(size_t)BB*HH*SS]; // [b][h][s] (transposed)
__device__ __nv_bfloat16 g_vtlo[(size_t)BB*HH*SS];

// split-K attention partials: 40 chunks per batch, 128 rows, 128 cols
#define NCHUNKS_PB 40
__device__ float g_opart[(size_t)BB*NCHUNKS_PB*128*128];   // 21 MB
__device__ float g_mpart[(size_t)BB*NCHUNKS_PB*128];
__device__ float g_lpart[(size_t)BB*NCHUNKS_PB*128];

// ---------------------------------------------------------------------------
// helpers
// ---------------------------------------------------------------------------
__device__ __forceinline__ uint32_t smem_u32(const void* p) {
    uint32_t a;
    asm("{ .reg .u64 t; cvta.to.shared.u64 t, %1; cvt.u32.u64 %0, t; }" : "=r"(a) : "l"(p));
    return a;
}
__device__ __forceinline__ void ldsm_x4(uint32_t* r, uint32_t addr) {
    asm volatile("ldmatrix.sync.aligned.m8n8.x4.shared.b16 {%0,%1,%2,%3}, [%4];"
                 : "=r"(r[0]), "=r"(r[1]), "=r"(r[2]), "=r"(r[3]) : "r"(addr));
}
__device__ __forceinline__ void mma16816(float* c, const uint32_t* a, const uint32_t* b) {
    asm volatile(
        "mma.sync.aligned.m16n8k16.row.col.f32.bf16.bf16.f32 "
        "{%0,%1,%2,%3}, {%4,%5,%6,%7}, {%8,%9}, {%0,%1,%2,%3};"
        : "+f"(c[0]), "+f"(c[1]), "+f"(c[2]), "+f"(c[3])
        : "r"(a[0]), "r"(a[1]), "r"(a[2]), "r"(a[3]), "r"(b[0]), "r"(b[1]));
}
__device__ __forceinline__ uint32_t pack_bf16(float lo_el, float hi_el) {
    uint32_t r;
    asm("cvt.rn.bf16x2.f32 %0, %1, %2;" : "=r"(r) : "f"(hi_el), "f"(lo_el));
    return r;
}
#define CP_ASYNC16(dst, src) \
    asm volatile("cp.async.cg.shared.global [%0], [%1], 16;" :: "r"(dst), "l"(src))
#define CP_COMMIT() asm volatile("cp.async.commit_group;" ::: "memory")
#define CP_WAIT1()  asm volatile("cp.async.wait_group 1;" ::: "memory")
#define CP_WAIT0()  asm volatile("cp.async.wait_group 0;" ::: "memory")

// ---------------------------------------------------------------------------
// Split-conversion kernels
// ---------------------------------------------------------------------------
__global__ void convert_x(const float* __restrict__ x) {
    size_t i = (size_t)blockIdx.x * blockDim.x + threadIdx.x;  // 8-elem index
    const float4 v0 = ((const float4*)x)[i * 2];
    const float4 v1 = ((const float4*)x)[i * 2 + 1];
    float a[8] = {v0.x, v0.y, v0.z, v0.w, v1.x, v1.y, v1.z, v1.w};
    __nv_bfloat16 h[8], l[8];
#pragma unroll
    for (int j = 0; j < 8; j++) {
        h[j] = __float2bfloat16(a[j]);
        l[j] = __float2bfloat16(a[j] - __bfloat162float(h[j]));
    }
    *(uint4*)&g_xhi[i * 8] = *(uint4*)h;
    *(uint4*)&g_xlo[i * 8] = *(uint4*)l;
}
__global__ void convert_w(const float* __restrict__ Wq, const float* __restrict__ Wk,
                          const float* __restrict__ Wv) {
    int idx = blockIdx.x * blockDim.x + threadIdx.x;   // [w][n][k]
    if (idx >= 3 * HH * DD) return;
    int wi = idx / (HH * DD);
    int rem = idx % (HH * DD);
    int n = rem / DD, k = rem % DD;
    const float* W = (wi == 0) ? Wq : (wi == 1) ? Wk : Wv;
    float val = W[(size_t)k * HH + n];
    __nv_bfloat16 hi = __float2bfloat16(val);
    __nv_bfloat16 lo = __float2bfloat16(val - __bfloat162float(hi));
    g_whi[idx] = hi;
    g_wlo[idx] = lo;
}

// ---------------------------------------------------------------------------
// QKV projection via warp-level bf16 split MMA.  M-tile 64 x N 128, 8 warps
// (2m x 4n, 32x32 per warp), 2 CTAs/SM, 768 CTAs for fine wave balance.
// ---------------------------------------------------------------------------
#define BK 32
#define ROWB 80
#define ABUF 5120            // 64 rows * 80B
#define BBUF 10240           // 128 rows * 80B
#define STG  (2*ABUF + 2*BBUF)   // 30720: [Ahi, Alo, Bhi, Blo]
#define QKV_SMEM (2 * STG)       // 61440

__global__ __launch_bounds__(256, 2)
void qkv_mma(const float* __restrict__ bq, const float* __restrict__ bk,
             const float* __restrict__ bv)
{
    extern __shared__ char smc[];
    const int tid  = threadIdx.x;
    const int lane = tid & 31;
    const int w    = tid >> 5;
    const int wm   = w & 1;       // 2 m-warps of 32 rows
    const int wn   = w >> 1;      // 4 n-warps of 32 cols
    const int which = blockIdx.y;
    const int m0 = blockIdx.x * 64;

    const __nv_bfloat16* srcB_hi = g_whi + (size_t)which * HH * DD;
    const __nv_bfloat16* srcB_lo = g_wlo + (size_t)which * HH * DD;
    const float* bias = (which == 0) ? bq : (which == 1) ? bk : bv;

    const uint32_t smem_base = smem_u32(smc);

    float acc[2][4][4];
#pragma unroll
    for (int mi = 0; mi < 2; mi++)
#pragma unroll
        for (int nt = 0; nt < 4; nt++)
#pragma unroll
            for (int e = 0; e < 4; e++) acc[mi][nt][e] = 0.f;

    auto load_stage = [&](int stage, int k0) {
        uint32_t stb = smem_base + (uint32_t)stage * STG;
        // A arrays: 64 rows x 4 chunks (64B) x 2 arrays = 512 chunks, 2/thread
#pragma unroll
        for (int i = 0; i < 2; i++) {
            int idx = i * 256 + tid;
            int arr = idx >> 8;
            int rem = idx & 255;
            int row = rem >> 2, part = rem & 3;
            const __nv_bfloat16* src = (arr ? g_xlo : g_xhi)
                + (size_t)(m0 + row) * DD + k0 + part * 8;
            CP_ASYNC16(stb + arr * ABUF + row * ROWB + part * 16, src);
        }
        // B arrays: 128 rows x 4 chunks x 2 arrays = 1024 chunks, 4/thread
#pragma unroll
        for (int i = 0; i < 4; i++) {
            int idx = i * 256 + tid;
            int arr = idx >> 9;
            int rem = idx & 511;
            int row = rem >> 2, part = rem & 3;
            const __nv_bfloat16* src = (arr ? srcB_lo : srcB_hi)
                + (size_t)row * DD + k0 + part * 8;
            CP_ASYNC16(stb + 2 * ABUF + arr * BBUF + row * ROWB + part * 16, src);
        }
    };

    load_stage(0, 0);
    CP_COMMIT();

    const int NIT = DD / BK;   // 32
    for (int it = 0; it < NIT; it++) {
        if (it + 1 < NIT) {
            load_stage((it + 1) & 1, (it + 1) * BK);
            CP_COMMIT();
            CP_WAIT1();
        } else {
            CP_WAIT0();
        }
        __syncthreads();

        const uint32_t stb  = smem_base + (uint32_t)((it & 1)) * STG;
        const uint32_t pAhi = stb;
        const uint32_t pAlo = stb + ABUF;
        const uint32_t pBhi = stb + 2 * ABUF;
        const uint32_t pBlo = stb + 2 * ABUF + BBUF;

#pragma unroll
        for (int ks = 0; ks < BK; ks += 16) {
            uint32_t ahi[2][4], alo[2][4];
#pragma unroll
            for (int mi = 0; mi < 2; mi++) {
                int row = wm * 32 + mi * 16 + (lane & 15);
                uint32_t off = (uint32_t)row * ROWB + (uint32_t)(ks + 8 * (lane >> 4)) * 2;
                ldsm_x4(ahi[mi], pAhi + off);
                ldsm_x4(alo[mi], pAlo + off);
            }
#pragma unroll
            for (int nt2 = 0; nt2 < 2; nt2++) {
                int j = lane >> 3;
                int nrow = wn * 32 + nt2 * 16 + 8 * (j >> 1) + (lane & 7);
                uint32_t boff = (uint32_t)nrow * ROWB + (uint32_t)(ks + 8 * (j & 1)) * 2;
                uint32_t bh[4], bl[4];
                ldsm_x4(bh, pBhi + boff);
                ldsm_x4(bl, pBlo + boff);
                mma16816(acc[0][nt2 * 2],     ahi[0], bh);
                mma16816(acc[1][nt2 * 2],     ahi[1], bh);
                mma16816(acc[0][nt2 * 2 + 1], ahi[0], bh + 2);
                mma16816(acc[1][nt2 * 2 + 1], ahi[1], bh + 2);
                mma16816(acc[0][nt2 * 2],     alo[0], bh);
                mma16816(acc[1][nt2 * 2],     alo[1], bh);
                mma16816(acc[0][nt2 * 2 + 1], alo[0], bh + 2);
                mma16816(acc[1][nt2 * 2 + 1], alo[1], bh + 2);
                mma16816(acc[0][nt2 * 2],     ahi[0], bl);
                mma16816(acc[1][nt2 * 2],     ahi[1], bl);
                mma16816(acc[0][nt2 * 2 + 1], ahi[0], bl + 2);
                mma16816(acc[1][nt2 * 2 + 1], ahi[1], bl + 2);
            }
        }
        __syncthreads();
    }

    // ---- epilogue: stage hi/lo bf16 tile in smem, write coalesced ----
    const int b  = m0 / SS;
    const int s0 = m0 % SS;
    __nv_bfloat16* sst = (__nv_bfloat16*)smc;
    // q/k staging: [m(64)][n(128)] stride 136; lo at elem 64*136=8704
    // v staging:   [n(128)][m(64)] stride 72;  lo at elem 128*72=9216
    const int QKSTR = 136;
    const int VSTR  = 72;
    const uint32_t lo_qk = 64 * QKSTR;
    const uint32_t lo_v  = 128 * VSTR;

#pragma unroll
    for (int mi = 0; mi < 2; mi++) {
#pragma unroll
        for (int half = 0; half < 2; half++) {
            int m = wm * 32 + mi * 16 + (lane >> 2) + 8 * half;
#pragma unroll
            for (int nt = 0; nt < 4; nt++) {
                int n = wn * 32 + nt * 8 + (lane & 3) * 2;
                float v0 = acc[mi][nt][half * 2 + 0] + bias[n];
                float v1 = acc[mi][nt][half * 2 + 1] + bias[n + 1];
                if (which == 0) { v0 *= 32.f; v1 *= 32.f; }
                __nv_bfloat16 h0 = __float2bfloat16(v0);
                __nv_bfloat16 h1 = __float2bfloat16(v1);
                __nv_bfloat16 l0 = __float2bfloat16(v0 - __bfloat162float(h0));
                __nv_bfloat16 l1 = __float2bfloat16(v1 - __bfloat162float(h1));
                if (which < 2) {
                    __nv_bfloat162 ph; ph.x = h0; ph.y = h1;
                    __nv_bfloat162 pl; pl.x = l0; pl.y = l1;
                    *(__nv_bfloat162*)&sst[m * QKSTR + n] = ph;
                    *(__nv_bfloat162*)&sst[lo_qk + m * QKSTR + n] = pl;
                } else {
                    sst[n * VSTR + m] = h0;
                    sst[(n + 1) * VSTR + m] = h1;
                    sst[lo_v + n * VSTR + m] = l0;
                    sst[lo_v + (n + 1) * VSTR + m] = l1;
                }
            }
        }
    }
    __syncthreads();

    if (which < 2) {
        __nv_bfloat16* dhi = (which == 0) ? g_qhi : g_khi;
        __nv_bfloat16* dlo = (which == 0) ? g_qlo : g_klo;
        const size_t gbase = ((size_t)b * SS + s0) * HH;
        // 64 rows x 16 chunks x 2 arrays = 2048 chunks -> 8 per thread
#pragma unroll
        for (int it = 0; it < 8; it++) {
            int idx = it * 256 + tid;
            int arr = idx >> 10;
            int rem = idx & 1023;
            int row = rem >> 4, c = rem & 15;
            uint4 val = *(const uint4*)&sst[(arr ? lo_qk : 0) + row * QKSTR + c * 8];
            *(uint4*)((arr ? dlo : dhi) + gbase + (size_t)row * HH + c * 8) = val;
        }
    } else {
        // 128 n-rows x 8 chunks x 2 arrays = 2048 chunks -> 8 per thread
#pragma unroll
        for (int it = 0; it < 8; it++) {
            int idx = it * 256 + tid;
            int arr = idx >> 10;
            int rem = idx & 1023;
            int row = rem >> 3, c = rem & 7;
            uint4 val = *(const uint4*)&sst[(arr ? lo_v : 0) + row * VSTR + c * 8];
            __nv_bfloat16* dst = (arr ? g_vtlo : g_vthi)
                + ((size_t)b * HH + row) * SS + s0 + c * 8;
            *(uint4*)dst = val;
        }
    }
}

// ---------------------------------------------------------------------------
// Split-K flash attention partials: TQ=128 (8 warps), chunks of <=8 k-tiles.
// Race-free pipeline (prefetch post-barrier).  Writes (o, m, l) partials.
// (unchanged from R12)
// ---------------------------------------------------------------------------
#define ATQ 128
#define ATK 64
#define KROWB 272   // Q/K smem row stride (256B + 16B pad)
#define VROWB 144   // V smem row stride (128B + 16B pad)
#define QB (128*KROWB)           // one Q array: 34816
#define K_OFF (2*QB)             // 69632
#define KB (64*KROWB)            // one K array: 17408
#define KSTG (2*KB)              // K stage (hi+lo): 34816
#define V_OFF (K_OFF + 2*KSTG)   // 139264
#define VB (128*VROWB)           // one V array: 18432
#define VSTG (2*VB)              // 36864
#define ATTN_SMEM (V_OFF + 2*VSTG)   // 212992
#define CHUNK 8                  // k-tiles per chunk

__global__ __launch_bounds__(256, 1)
void attn_mma(void)
{
    extern __shared__ char smc[];
    const uint32_t sb = smem_u32(smc);
    const int tid  = threadIdx.x;
    const int lane = tid & 31;
    const int w    = tid >> 5;                 // 0..7, rows w*16..w*16+15
    const int b    = blockIdx.y;
    const int id   = blockIdx.x;               // chunk id within batch (0..39)

    // ---- map id -> (qt, kstart, kend), qt descending (heavy first) ----
    int qt = 15, kstart = 0, kend = 0;
    {
        int c = id;
        for (int q = 15; q >= 0; q--) {
            int nk = 2 * q + 2;
            int np = (nk + CHUNK - 1) >> 3;
            if (c < np) { qt = q; kstart = c * CHUNK; kend = min(kstart + CHUNK, nk); break; }
            c -= np;
        }
    }
    const int q0 = qt * ATQ;
    const int pid = b * NCHUNKS_PB + id;       // scratch slot

    // ---- issue Q tile loads (hi+lo) ----
    {
        const __nv_bfloat16* qhib = g_qhi + ((size_t)b * SS + q0) * HH;
        const __nv_bfloat16* qlob = g_qlo + ((size_t)b * SS + q0) * HH;
#pragma unroll
        for (int it = 0; it < 16; it++) {
            int idx = it * 256 + tid;          // 0..4095
            int arr = idx >> 11;
            int rem = idx & 2047;
            int r = rem >> 4, c = rem & 15;
            const __nv_bfloat16* src = (arr ? qlob : qhib) + (size_t)r * HH + c * 8;
            CP_ASYNC16(sb + arr * QB + r * KROWB + c * 16, src);
        }
    }

    auto load_kv = [&](int stg, int ktile) {
        const int k0 = ktile * ATK;
        uint32_t kb = sb + K_OFF + stg * KSTG;
        const __nv_bfloat16* khb = g_khi + ((size_t)b * SS + k0) * HH;
        const __nv_bfloat16* klb = g_klo + ((size_t)b * SS + k0) * HH;
#pragma unroll
        for (int it = 0; it < 8; it++) {
            int idx = it * 256 + tid;          // 0..2047
            int arr = idx >> 10;
            int rem = idx & 1023;
            int r = rem >> 4, c = rem & 15;    // 64 rows x 16 chunks
            const __nv_bfloat16* src = (arr ? klb : khb) + (size_t)r * HH + c * 8;
            CP_ASYNC16(kb + arr * KB + r * KROWB + c * 16, src);
        }
        uint32_t vb = sb + V_OFF + stg * VSTG;
        const __nv_bfloat16* vhb = g_vthi + (size_t)b * HH * SS + k0;
        const __nv_bfloat16* vlb = g_vtlo + (size_t)b * HH * SS + k0;
#pragma unroll
        for (int it = 0; it < 8; it++) {
            int idx = it * 256 + tid;          // 0..2047
            int arr = idx >> 10;
            int rem = idx & 1023;
            int r = rem >> 3, c = rem & 7;     // 128 rows x 8 chunks
            const __nv_bfloat16* src = (arr ? vlb : vhb) + (size_t)r * SS + c * 8;
            CP_ASYNC16(vb + arr * VB + r * VROWB + c * 16, src);
        }
    };

    load_kv(kstart & 1, kstart);
    CP_COMMIT();   // group: Q + KV(kstart)

    float o[16][4];
#pragma unroll
    for (int nt = 0; nt < 16; nt++)
#pragma unroll
        for (int e = 0; e < 4; e++) o[nt][e] = 0.f;
    float m0r = -1e30f, m1r = -1e30f, l0 = 0.f, l1 = 0.f;
    uint32_t qh[8][4], ql[8][4];

    for (int kt = kstart; kt < kend; kt++) {
        CP_WAIT0();          // KV(kt) (and Q on first iter) complete
        __syncthreads();     // ALL warps past previous iteration's reads

        if (kt == kstart) {
            int arow = w * 16 + (lane & 15);
            uint32_t abase = (uint32_t)arow * KROWB + (uint32_t)(8 * (lane >> 4)) * 2;
#pragma unroll
            for (int ks = 0; ks < 8; ks++) {
                ldsm_x4(qh[ks], sb + abase + ks * 32);
                ldsm_x4(ql[ks], sb + QB + abase + ks * 32);
            }
        }

        // ---- prefetch KV(kt+1): safe (post-barrier), overlaps compute ----
        if (kt + 1 < kend) {
            load_kv((kt + 1) & 1, kt + 1);
            CP_COMMIT();
        }

        const uint32_t kbase = sb + K_OFF + (kt & 1) * KSTG;
        const uint32_t vbase = sb + V_OFF + (kt & 1) * VSTG;

        // warp fully masked for this tile? (all cols > all its rows)
        const bool dead = (kt * ATK > q0 + w * 16 + 15);

        // ---- S = Q K^T (pre-scaled x32) ----
        float S[8][4];
#pragma unroll
        for (int nt = 0; nt < 8; nt++)
#pragma unroll
            for (int e = 0; e < 4; e++) S[nt][e] = dead ? -1e30f : 0.f;

        if (!dead) {
#pragma unroll
            for (int ks = 0; ks < 8; ks++) {
#pragma unroll
                for (int nt2 = 0; nt2 < 4; nt2++) {
                    int j = lane >> 3;
                    int nrow = nt2 * 16 + 8 * (j >> 1) + (lane & 7);
                    uint32_t boff = (uint32_t)nrow * KROWB + (uint32_t)(ks * 16 + 8 * (j & 1)) * 2;
                    uint32_t bh[4], bl[4];
                    ldsm_x4(bh, kbase + boff);
                    ldsm_x4(bl, kbase + KB + boff);
                    mma16816(S[nt2 * 2],     qh[ks], bh);
                    mma16816(S[nt2 * 2 + 1], qh[ks], bh + 2);
                    mma16816(S[nt2 * 2],     ql[ks], bh);
                    mma16816(S[nt2 * 2 + 1], ql[ks], bh + 2);
                    mma16816(S[nt2 * 2],     qh[ks], bl);
                    mma16816(S[nt2 * 2 + 1], qh[ks], bl + 2);
                }
            }
        }

        // ---- causal mask (only tiles that can touch the diagonal) ----
        const int r  = lane >> 2;
        const int c2 = (lane & 3) * 2;
        if (kt >= 2 * qt && !dead) {
            int gr0l = q0 + w * 16 + r;
            int gr1l = gr0l + 8;
            int gc0 = kt * ATK + c2;
#pragma unroll
            for (int nt = 0; nt < 8; nt++) {
                int col0 = gc0 + nt * 8;
                if (col0 > gr0l)     S[nt][0] = -1e30f;
                if (col0 + 1 > gr0l) S[nt][1] = -1e30f;
                if (col0 > gr1l)     S[nt][2] = -1e30f;
                if (col0 + 1 > gr1l) S[nt][3] = -1e30f;
            }
        }

        // ---- online softmax ----
        float mo0 = m0r, mo1 = m1r;
#pragma unroll
        for (int nt = 0; nt < 8; nt++) {
            m0r = fmaxf(m0r, fmaxf(S[nt][0], S[nt][1]));
            m1r = fmaxf(m1r, fmaxf(S[nt][2], S[nt][3]));
        }
        m0r = fmaxf(m0r, __shfl_xor_sync(0xffffffffu, m0r, 1));
        m0r = fmaxf(m0r, __shfl_xor_sync(0xffffffffu, m0r, 2));
        m1r = fmaxf(m1r, __shfl_xor_sync(0xffffffffu, m1r, 1));
        m1r = fmaxf(m1r, __shfl_xor_sync(0xffffffffu, m1r, 2));
        float a0 = __expf(mo0 - m0r);
        float a1 = __expf(mo1 - m1r);
#pragma unroll
        for (int nt = 0; nt < 16; nt++) {
            o[nt][0] *= a0; o[nt][1] *= a0;
            o[nt][2] *= a1; o[nt][3] *= a1;
        }
        float sum0 = 0.f, sum1 = 0.f;
#pragma unroll
        for (int nt = 0; nt < 8; nt++) {
            S[nt][0] = __expf(S[nt][0] - m0r);
            S[nt][1] = __expf(S[nt][1] - m0r);
            S[nt][2] = __expf(S[nt][2] - m1r);
            S[nt][3] = __expf(S[nt][3] - m1r);
            sum0 += S[nt][0] + S[nt][1];
            sum1 += S[nt][2] + S[nt][3];
        }
        l0 = l0 * a0 + sum0;
        l1 = l1 * a1 + sum1;

        if (!dead) {
            // ---- pack P into A-fragments (hi/lo bf16) ----
            uint32_t ph[4][4], pl[4][4];
#pragma unroll
            for (int kp = 0; kp < 4; kp++) {
#pragma unroll
                for (int half = 0; half < 2; half++) {
                    int nt = 2 * kp + half;
                    float p0 = S[nt][0], p1 = S[nt][1];
                    float p2 = S[nt][2], p3 = S[nt][3];
                    float h0 = __bfloat162float(__float2bfloat16(p0));
                    float h1 = __bfloat162float(__float2bfloat16(p1));
                    float h2 = __bfloat162float(__float2bfloat16(p2));
                    float h3 = __bfloat162float(__float2bfloat16(p3));
                    ph[kp][half * 2 + 0] = pack_bf16(h0, h1);
                    ph[kp][half * 2 + 1] = pack_bf16(h2, h3);
                    pl[kp][half * 2 + 0] = pack_bf16(p0 - h0, p1 - h1);
                    pl[kp][half * 2 + 1] = pack_bf16(p2 - h2, p3 - h3);
                }
            }

            // ---- O += P V ----
#pragma unroll
            for (int ks = 0; ks < 4; ks++) {
#pragma unroll
                for (int nt2 = 0; nt2 < 8; nt2++) {
                    int j = lane >> 3;
                    int nrow = nt2 * 16 + 8 * (j >> 1) + (lane & 7);
                    uint32_t boff = (uint32_t)nrow * VROWB + (uint32_t)(ks * 16 + 8 * (j & 1)) * 2;
                    uint32_t vh[4], vl[4];
                    ldsm_x4(vh, vbase + boff);
                    ldsm_x4(vl, vbase + VB + boff);
                    mma16816(o[nt2 * 2],     ph[ks], vh);
                    mma16816(o[nt2 * 2 + 1], ph[ks], vh + 2);
                    mma16816(o[nt2 * 2],     pl[ks], vh);
                    mma16816(o[nt2 * 2 + 1], pl[ks], vh + 2);
                    mma16816(o[nt2 * 2],     ph[ks], vl);
                    mma16816(o[nt2 * 2 + 1], ph[ks], vl + 2);
                }
            }
        }
    }

    // ---- epilogue: write UNNORMALIZED partial (o, m, l) to scratch ----
    l0 += __shfl_xor_sync(0xffffffffu, l0, 1);
    l0 += __shfl_xor_sync(0xffffffffu, l0, 2);
    l1 += __shfl_xor_sync(0xffffffffu, l1, 1);
    l1 += __shfl_xor_sync(0xffffffffu, l1, 2);

    const int lr0 = w * 16 + (lane >> 2);      // local row in tile
    const int lr1 = lr0 + 8;
    const int cb  = (lane & 3) * 2;
    float* obase = g_opart + (size_t)pid * 128 * 128;
#pragma unroll
    for (int nt = 0; nt < 16; nt++) {
        int col = nt * 8 + cb;
        *(float2*)&obase[(size_t)lr0 * 128 + col] = make_float2(o[nt][0], o[nt][1]);
        *(float2*)&obase[(size_t)lr1 * 128 + col] = make_float2(o[nt][2], o[nt][3]);
    }
    if ((lane & 3) == 0) {
        g_mpart[(size_t)pid * 128 + lr0] = m0r;
        g_mpart[(size_t)pid * 128 + lr1] = m1r;
        g_lpart[(size_t)pid * 128 + lr0] = l0;
        g_lpart[(size_t)pid * 128 + lr1] = l1;
    }
}

// ---------------------------------------------------------------------------
// Combine split-K partials: out = sum_i e^{m_i - M} o_i / sum_i e^{m_i - M} l_i
// grid (16 qtiles, 8 batches, 4 col-quarters), 128 threads (one row each).
// ---------------------------------------------------------------------------
__global__ __launch_bounds__(128)
void attn_combine(float* __restrict__ out)
{
    const int qt = blockIdx.x;
    const int b  = blockIdx.y;
    const int c0 = blockIdx.z * 32;
    const int np = (2 * qt + 2 + CHUNK - 1) >> 3;
    int off = 0;
    for (int q = 15; q > qt; q--) off += (2 * q + 2 + CHUNK - 1) >> 3;
    const int pid0 = b * NCHUNKS_PB + off;

    const int row = threadIdx.x;               // 0..127

    float m[4], lv[4];
    float M = -1e30f;
    for (int p = 0; p < np; p++) {
        m[p]  = g_mpart[(size_t)(pid0 + p) * 128 + row];
        lv[p] = g_lpart[(size_t)(pid0 + p) * 128 + row];
        M = fmaxf(M, m[p]);
    }
    float wgt[4];
    float L = 0.f;
    for (int p = 0; p < np; p++) {
        wgt[p] = __expf(m[p] - M);
        L += wgt[p] * lv[p];
    }
    const float inv = 1.f / L;

    float* dst = out + ((size_t)b * SS + qt * ATQ + row) * HH + c0;
#pragma unroll
    for (int c4 = 0; c4 < 8; c4++) {
        float4 acc = make_float4(0.f, 0.f, 0.f, 0.f);
        for (int p = 0; p < np; p++) {
            const float4 v = *(const float4*)&g_opart[((size_t)(pid0 + p) * 128 + row) * 128 + c0 + c4 * 4];
            acc.x += wgt[p] * v.x;
            acc.y += wgt[p] * v.y;
            acc.z += wgt[p] * v.z;
            acc.w += wgt[p] * v.w;
        }
        acc.x *= inv; acc.y *= inv; acc.z *= inv; acc.w *= inv;
        *(float4*)&dst[c4 * 4] = acc;
    }
}

// ---------------------------------------------------------------------------
extern "C" void kernel_launch(void* const* d_in, const int* in_sizes, int n_in,
                              void* d_out, int out_size)
{
    const float* x  = (const float*)d_in[0];
    const float* Wq = (const float*)d_in[1];
    const float* bq = (const float*)d_in[2];
    const float* Wk = (const float*)d_in[3];
    const float* bk = (const float*)d_in[4];
    const float* Wv = (const float*)d_in[5];
    const float* bv = (const float*)d_in[6];
    float* out = (float*)d_out;

    cudaFuncSetAttribute(qkv_mma, cudaFuncAttributeMaxDynamicSharedMemorySize, QKV_SMEM);
    cudaFuncSetAttribute(attn_mma, cudaFuncAttributeMaxDynamicSharedMemorySize, ATTN_SMEM);

    convert_x<<<(MTOT * DD / 8) / 256, 256>>>(x);
    convert_w<<<(3 * HH * DD + 255) / 256, 256>>>(Wq, Wk, Wv);
    qkv_mma<<<dim3(MTOT / 64, 3), 256, QKV_SMEM>>>(bq, bk, bv);
    attn_mma<<<dim3(NCHUNKS_PB, BB), 256, ATTN_SMEM>>>();
    attn_combine<<<dim3(SS / ATQ, BB, 4), 128>>>(out);
}